// round 1
// baseline (speedup 1.0000x reference)
#include <cuda_runtime.h>
#include <math.h>

// ---------------------------------------------------------------------------
// ConvolutionalAttention2D: linear attention over 2D feature maps.
//   q,k,v = W{q,k,v} @ x      (per-pixel 1x1 conv == channel GEMM)
//   phi = elu(.)+1
//   qv[b]   = phi_q[b] @ phi_v[b]^T            [256,256]
//   out[b]  = (Wo @ qv[b]) @ phi_k[b] + bo     <-- reassociated: tiny 256^3 GEMM
// Shapes: B=16, C=256, N=H*W=4096.
// ---------------------------------------------------------------------------

#define BM 64
#define BN 64
#define BK 16

#define NB    16
#define NC    256
#define NPIX  4096
#define PHI_B (768 * NPIX)       // per-batch stride in g_phi (q rows 0-255, k 256-511, v 512-767)
#define QV_N  (NB * NC * NC)     // 16*65536
#define KSPLIT 8

// Scratch (allocation-free rule: __device__ globals)
__device__ __align__(16) float g_phi[NB * 768 * NPIX];        // 201 MB
__device__ __align__(16) float g_qvp[KSPLIT * QV_N];          // 32 MB  split-K partials
__device__ __align__(16) float g_qv [QV_N];                   // 4 MB
__device__ __align__(16) float g_M  [QV_N];                   // 4 MB  (Wo @ qv)

// ---------------------------------------------------------------------------
// One 64x64 output tile, 256 threads, each thread 4x4 accumulators.
// TB=false: C = A[M,K] * B[K,N]   (both row-major)
// TB=true : C = A[M,K] * B[N,K]^T (dot over contiguous K in both)
// EPI: 0 = none, 1 = phi (elu+1), 2 = +bias[row]
// A,B,C pre-offset to the tile origin by the caller.
// ---------------------------------------------------------------------------
template <bool TB, int EPI>
__device__ __forceinline__ void gemm_tile(
    const float* __restrict__ A, int lda,
    const float* __restrict__ B, int ldb,
    float* __restrict__ C, int ldc,
    int K, const float* __restrict__ bias)
{
    __shared__ float As[BK][BM + 1];
    __shared__ float Bs[BK][BN + 1];

    const int tid  = threadIdx.x;     // 0..255
    const int tx   = tid & 15;
    const int ty   = tid >> 4;
    const int lrow = tid >> 2;        // 0..63   (K-major tile loads)
    const int lk   = (tid & 3) << 2;  // 0,4,8,12

    float acc[4][4];
#pragma unroll
    for (int i = 0; i < 4; i++)
#pragma unroll
        for (int j = 0; j < 4; j++) acc[i][j] = 0.f;

    for (int k0 = 0; k0 < K; k0 += BK) {
        // A tile: rows are M, contiguous K -> transpose into As[k][m]
        float4 av = *reinterpret_cast<const float4*>(A + (size_t)lrow * lda + k0 + lk);
        As[lk + 0][lrow] = av.x;
        As[lk + 1][lrow] = av.y;
        As[lk + 2][lrow] = av.z;
        As[lk + 3][lrow] = av.w;

        if (TB) {
            // B tile: rows are N, contiguous K -> transpose into Bs[k][n]
            float4 bv = *reinterpret_cast<const float4*>(B + (size_t)lrow * ldb + k0 + lk);
            Bs[lk + 0][lrow] = bv.x;
            Bs[lk + 1][lrow] = bv.y;
            Bs[lk + 2][lrow] = bv.z;
            Bs[lk + 3][lrow] = bv.w;
        } else {
            // B tile: rows are K, contiguous N
            float4 bv = *reinterpret_cast<const float4*>(B + (size_t)(k0 + ty) * ldb + (tx << 2));
            Bs[ty][(tx << 2) + 0] = bv.x;
            Bs[ty][(tx << 2) + 1] = bv.y;
            Bs[ty][(tx << 2) + 2] = bv.z;
            Bs[ty][(tx << 2) + 3] = bv.w;
        }
        __syncthreads();

#pragma unroll
        for (int kk = 0; kk < BK; kk++) {
            float a0 = As[kk][(ty << 2) + 0];
            float a1 = As[kk][(ty << 2) + 1];
            float a2 = As[kk][(ty << 2) + 2];
            float a3 = As[kk][(ty << 2) + 3];
            float b0 = Bs[kk][(tx << 2) + 0];
            float b1 = Bs[kk][(tx << 2) + 1];
            float b2 = Bs[kk][(tx << 2) + 2];
            float b3 = Bs[kk][(tx << 2) + 3];
            acc[0][0] += a0 * b0; acc[0][1] += a0 * b1; acc[0][2] += a0 * b2; acc[0][3] += a0 * b3;
            acc[1][0] += a1 * b0; acc[1][1] += a1 * b1; acc[1][2] += a1 * b2; acc[1][3] += a1 * b3;
            acc[2][0] += a2 * b0; acc[2][1] += a2 * b1; acc[2][2] += a2 * b2; acc[2][3] += a2 * b3;
            acc[3][0] += a3 * b0; acc[3][1] += a3 * b1; acc[3][2] += a3 * b2; acc[3][3] += a3 * b3;
        }
        __syncthreads();
    }

#pragma unroll
    for (int i = 0; i < 4; i++) {
        int row = (ty << 2) + i;
        float bval = (EPI == 2) ? bias[row] : 0.f;
#pragma unroll
        for (int j = 0; j < 4; j++) {
            float v = acc[i][j];
            if (EPI == 1) v = (v > 0.f) ? (v + 1.f) : expf(v);   // elu(v)+1
            if (EPI == 2) v += bval;
            C[(size_t)row * ldc + (tx << 2) + j] = v;
        }
    }
}

// --- Stage 1: phi(W{q,k,v} @ x) -> g_phi  -----------------------------------
// grid (NPIX/64=64, 768/64=12, B=16)
__global__ __launch_bounds__(256) void k_qkv(
    const float* __restrict__ x,
    const float* __restrict__ Wq,
    const float* __restrict__ Wk,
    const float* __restrict__ Wv)
{
    const int b    = blockIdx.z;
    const int rblk = blockIdx.y;                     // 0..11
    const float* W = (rblk < 4) ? Wq : ((rblk < 8) ? Wk : Wv);
    const float* A = W + (size_t)((rblk & 3) * 64) * NC;
    const float* B = x + (size_t)b * NC * NPIX + blockIdx.x * 64;
    float* C = g_phi + (size_t)b * PHI_B + (size_t)(rblk * 64) * NPIX + blockIdx.x * 64;
    gemm_tile<false, 1>(A, NC, B, NPIX, C, NPIX, NC, nullptr);
}

// --- Stage 2: qv partials (split-K over N=4096) -----------------------------
// grid (4, 4, B*KSPLIT=128)
__global__ __launch_bounds__(256) void k_qv()
{
    const int b = blockIdx.z >> 3;
    const int s = blockIdx.z & 7;
    const int kofs = s * (NPIX / KSPLIT);            // 512-wide K chunk
    const float* base = g_phi + (size_t)b * PHI_B;
    const float* A = base + (size_t)(blockIdx.y * 64) * NPIX + kofs;          // phi_q rows
    const float* B = base + (size_t)(512 + blockIdx.x * 64) * NPIX + kofs;    // phi_v rows
    float* C = g_qvp + (size_t)s * QV_N + (size_t)b * NC * NC
             + (size_t)(blockIdx.y * 64) * NC + blockIdx.x * 64;
    gemm_tile<true, 0>(A, NPIX, B, NPIX, C, NC, NPIX / KSPLIT, nullptr);
}

// --- Stage 2b: reduce split-K partials --------------------------------------
__global__ __launch_bounds__(256) void k_qv_reduce()
{
    const size_t i = (size_t)blockIdx.x * 256 + threadIdx.x;
    float sv = 0.f;
#pragma unroll
    for (int s = 0; s < KSPLIT; s++) sv += g_qvp[(size_t)s * QV_N + i];
    g_qv[i] = sv;
}

// --- Stage 3: M[b] = Wo @ qv[b]  (tiny) -------------------------------------
// grid (4, 4, 16)
__global__ __launch_bounds__(256) void k_m(const float* __restrict__ Wo)
{
    const int b = blockIdx.z;
    const float* A = Wo + (size_t)(blockIdx.y * 64) * NC;
    const float* B = g_qv + (size_t)b * NC * NC + blockIdx.x * 64;
    float* C = g_M + (size_t)b * NC * NC + (size_t)(blockIdx.y * 64) * NC + blockIdx.x * 64;
    gemm_tile<false, 0>(A, NC, B, NC, C, NC, NC, nullptr);
}

// --- Stage 4: out[b] = M[b] @ phi_k[b] + bo ---------------------------------
// grid (64, 4, 16)
__global__ __launch_bounds__(256) void k_out(const float* __restrict__ bo,
                                             float* __restrict__ out)
{
    const int b = blockIdx.z;
    const float* A = g_M + (size_t)b * NC * NC + (size_t)(blockIdx.y * 64) * NC;
    const float* B = g_phi + (size_t)b * PHI_B + (size_t)(256 + 0) * NPIX + blockIdx.x * 64;
    float* C = out + (size_t)b * NC * NPIX + (size_t)(blockIdx.y * 64) * NPIX + blockIdx.x * 64;
    gemm_tile<false, 2>(A, NC, B, NPIX, C, NPIX, NC, bo + blockIdx.y * 64);
}

// ---------------------------------------------------------------------------
extern "C" void kernel_launch(void* const* d_in, const int* in_sizes, int n_in,
                              void* d_out, int out_size)
{
    const float* x  = (const float*)d_in[0];
    const float* Wq = (const float*)d_in[1];
    const float* Wk = (const float*)d_in[2];
    const float* Wv = (const float*)d_in[3];
    const float* Wo = (const float*)d_in[4];
    const float* bo = (const float*)d_in[5];
    float* out = (float*)d_out;

    k_qkv<<<dim3(64, 12, 16), 256>>>(x, Wq, Wk, Wv);
    k_qv<<<dim3(4, 4, NB * KSPLIT), 256>>>();
    k_qv_reduce<<<dim3(QV_N / 256), 256>>>();
    k_m<<<dim3(4, 4, 16), 256>>>(Wo);
    k_out<<<dim3(64, 4, 16), 256>>>(bo, out);
}

// round 3
// speedup vs baseline: 4.0747x; 4.0747x over previous
#include <cuda_runtime.h>
#include <math.h>
#include <stdint.h>

// ---------------------------------------------------------------------------
// ConvolutionalAttention2D via TF32 tensor cores (mma.sync m16n8k8).
//   q,k,v = W{q,k,v} @ x ; phi = elu+1
//   qv[b]  = phi_q[b] @ phi_v[b]^T
//   out[b] = (Wo @ qv[b]) @ phi_k[b] + bo       (reassociated)
// B=16, C=256, N=H*W=4096.
// ---------------------------------------------------------------------------

#define NB    16
#define NC    256
#define NPIX  4096
#define PHI_B (768 * NPIX)
#define QV_N  (NB * NC * NC)
#define KSPLIT 8

__device__ __align__(16) float g_phi[NB * 768 * NPIX];   // 201 MB
__device__ __align__(16) float g_qvp[KSPLIT * QV_N];     // 32 MB
__device__ __align__(16) float g_qv [QV_N];              // 4 MB
__device__ __align__(16) float g_M  [QV_N];              // 4 MB

__device__ __forceinline__ float tf32r(float x) {
    uint32_t u;
    asm("cvt.rna.tf32.f32 %0, %1;" : "=r"(u) : "f"(x));
    return __uint_as_float(u);
}

__device__ __forceinline__ void mma_tf32(float c[4],
                                          uint32_t a0, uint32_t a1, uint32_t a2, uint32_t a3,
                                          uint32_t b0, uint32_t b1) {
    asm volatile(
        "mma.sync.aligned.m16n8k8.row.col.f32.tf32.tf32.f32 "
        "{%0,%1,%2,%3}, {%4,%5,%6,%7}, {%8,%9}, {%0,%1,%2,%3};\n"
        : "+f"(c[0]), "+f"(c[1]), "+f"(c[2]), "+f"(c[3])
        : "r"(a0), "r"(a1), "r"(a2), "r"(a3), "r"(b0), "r"(b1));
}

// ---------------------------------------------------------------------------
// 128x128 output tile, 256 threads (8 warps as 4Mx2N; warp tile 32x64).
// TB=false: C = A[M,K] * B[K,N]    (B N-contiguous)
// TB=true : C = A[M,K] * B[N,K]^T  (B K-contiguous)
// EPI: 0 none, 1 phi(elu+1), 2 +bias[row]
// A,B,C pre-offset to tile origin. K multiple of 32.
// ---------------------------------------------------------------------------
template <bool TB, int EPI>
__device__ __forceinline__ void gemm_tile_tc(
    const float* __restrict__ A, int lda,
    const float* __restrict__ B, int ldb,
    float* __restrict__ C, int ldc,
    int K, const float* __restrict__ bias)
{
    // As: row-major [m][k], stride 36 -> frag-load bank = (4g+t4)%32, conflict-free
    __shared__ float As[128][36];
    constexpr int BSR = TB ? 128 : 32;
    constexpr int BSC = TB ? 36  : 136;   // 136 % 32 == 8 -> bank = 8*t4+g, conflict-free
    __shared__ float Bs[BSR][BSC];

    const int tid  = threadIdx.x;
    const int warp = tid >> 5;
    const int lane = tid & 31;
    const int g    = lane >> 2;      // 0..7
    const int t4   = lane & 3;       // 0..3
    const int wm   = (warp & 3) * 32;
    const int wn   = (warp >> 2) * 64;

    float acc[2][8][4];
#pragma unroll
    for (int i = 0; i < 2; i++)
#pragma unroll
        for (int j = 0; j < 8; j++)
#pragma unroll
            for (int r = 0; r < 4; r++) acc[i][j][r] = 0.f;

    const int ar = tid >> 3;          // 0..31
    const int ak = (tid & 7) << 2;    // 0,4,..,28
    const int bk = tid >> 5;          // 0..7   (TB=false)
    const int bn = (tid & 31) << 2;   // 0..124 (TB=false)

    for (int k0 = 0; k0 < K; k0 += 32) {
        // ---- A tile: [128][32], rows M, contiguous K ----
#pragma unroll
        for (int p = 0; p < 4; p++) {
            int row = ar + 32 * p;
            float4 v = *reinterpret_cast<const float4*>(A + (size_t)row * lda + k0 + ak);
            As[row][ak + 0] = tf32r(v.x);
            As[row][ak + 1] = tf32r(v.y);
            As[row][ak + 2] = tf32r(v.z);
            As[row][ak + 3] = tf32r(v.w);
        }
        // ---- B tile ----
        if (TB) {
#pragma unroll
            for (int p = 0; p < 4; p++) {
                int row = ar + 32 * p;   // row = n
                float4 v = *reinterpret_cast<const float4*>(B + (size_t)row * ldb + k0 + ak);
                Bs[row][ak + 0] = tf32r(v.x);
                Bs[row][ak + 1] = tf32r(v.y);
                Bs[row][ak + 2] = tf32r(v.z);
                Bs[row][ak + 3] = tf32r(v.w);
            }
        } else {
#pragma unroll
            for (int p = 0; p < 4; p++) {
                int k = bk + 8 * p;
                float4 v = *reinterpret_cast<const float4*>(B + (size_t)(k0 + k) * ldb + bn);
                float4 w;
                w.x = tf32r(v.x); w.y = tf32r(v.y); w.z = tf32r(v.z); w.w = tf32r(v.w);
                *reinterpret_cast<float4*>(&Bs[k][bn]) = w;
            }
        }
        __syncthreads();

#pragma unroll
        for (int ks = 0; ks < 4; ks++) {
            const int kb = ks * 8;
            uint32_t af[2][4];
#pragma unroll
            for (int i = 0; i < 2; i++) {
                int r0 = wm + 16 * i + g;
                af[i][0] = __float_as_uint(As[r0    ][kb + t4    ]);
                af[i][1] = __float_as_uint(As[r0 + 8][kb + t4    ]);
                af[i][2] = __float_as_uint(As[r0    ][kb + t4 + 4]);
                af[i][3] = __float_as_uint(As[r0 + 8][kb + t4 + 4]);
            }
            uint32_t bf[8][2];
#pragma unroll
            for (int j = 0; j < 8; j++) {
                int n = wn + 8 * j + g;
                if (TB) {
                    bf[j][0] = __float_as_uint(Bs[n][kb + t4    ]);
                    bf[j][1] = __float_as_uint(Bs[n][kb + t4 + 4]);
                } else {
                    bf[j][0] = __float_as_uint(Bs[kb + t4    ][n]);
                    bf[j][1] = __float_as_uint(Bs[kb + t4 + 4][n]);
                }
            }
#pragma unroll
            for (int i = 0; i < 2; i++)
#pragma unroll
                for (int j = 0; j < 8; j++)
                    mma_tf32(acc[i][j], af[i][0], af[i][1], af[i][2], af[i][3],
                             bf[j][0], bf[j][1]);
        }
        __syncthreads();
    }

    // ---- epilogue: c frag (i,j): rows wm+16i+g (+8), cols wn+8j+2*t4 (+1) ----
#pragma unroll
    for (int i = 0; i < 2; i++) {
#pragma unroll
        for (int h = 0; h < 2; h++) {
            int row = wm + 16 * i + g + 8 * h;
            float bval = (EPI == 2) ? bias[row] : 0.f;
#pragma unroll
            for (int j = 0; j < 8; j++) {
                float v0 = acc[i][j][2 * h + 0];
                float v1 = acc[i][j][2 * h + 1];
                if (EPI == 1) {
                    v0 = (v0 > 0.f) ? (v0 + 1.f) : expf(v0);
                    v1 = (v1 > 0.f) ? (v1 + 1.f) : expf(v1);
                }
                if (EPI == 2) { v0 += bval; v1 += bval; }
                float2 o = make_float2(v0, v1);
                *reinterpret_cast<float2*>(C + (size_t)row * ldc + wn + 8 * j + 2 * t4) = o;
            }
        }
    }
}

// --- Stage 1: phi(W{q,k,v} @ x) -> g_phi ; grid (32, 6, 16) ------------------
__global__ __launch_bounds__(256) void k_qkv(
    const float* __restrict__ x,
    const float* __restrict__ Wq,
    const float* __restrict__ Wk,
    const float* __restrict__ Wv)
{
    const int b  = blockIdx.z;
    const int rb = blockIdx.y;                       // 0..5 (128 rows each)
    const float* W = (rb < 2) ? Wq : ((rb < 4) ? Wk : Wv);
    const float* A = W + (size_t)((rb & 1) * 128) * NC;
    const float* B = x + (size_t)b * NC * NPIX + blockIdx.x * 128;
    float* C = g_phi + (size_t)b * PHI_B + (size_t)(rb * 128) * NPIX + blockIdx.x * 128;
    gemm_tile_tc<false, 1>(A, NC, B, NPIX, C, NPIX, NC, nullptr);
}

// --- Stage 2: qv split-K partials ; grid (2, 2, 128) ------------------------
__global__ __launch_bounds__(256) void k_qv()
{
    const int b = blockIdx.z >> 3;
    const int s = blockIdx.z & 7;
    const int kofs = s * (NPIX / KSPLIT);
    const float* base = g_phi + (size_t)b * PHI_B;
    const float* A = base + (size_t)(blockIdx.y * 128) * NPIX + kofs;        // phi_q
    const float* B = base + (size_t)(512 + blockIdx.x * 128) * NPIX + kofs;  // phi_v
    float* C = g_qvp + (size_t)s * QV_N + (size_t)b * NC * NC
             + (size_t)(blockIdx.y * 128) * NC + blockIdx.x * 128;
    gemm_tile_tc<true, 0>(A, NPIX, B, NPIX, C, NC, NPIX / KSPLIT, nullptr);
}

// --- Stage 2b: reduce partials ----------------------------------------------
__global__ __launch_bounds__(256) void k_qv_reduce()
{
    const size_t i = (size_t)blockIdx.x * 256 + threadIdx.x;
    float sv = 0.f;
#pragma unroll
    for (int s = 0; s < KSPLIT; s++) sv += g_qvp[(size_t)s * QV_N + i];
    g_qv[i] = sv;
}

// --- Stage 3: M[b] = Wo @ qv[b] ; grid (2, 2, 16) ---------------------------
__global__ __launch_bounds__(256) void k_m(const float* __restrict__ Wo)
{
    const int b = blockIdx.z;
    const float* A = Wo + (size_t)(blockIdx.y * 128) * NC;
    const float* B = g_qv + (size_t)b * NC * NC + blockIdx.x * 128;
    float* C = g_M + (size_t)b * NC * NC + (size_t)(blockIdx.y * 128) * NC + blockIdx.x * 128;
    gemm_tile_tc<false, 0>(A, NC, B, NC, C, NC, NC, nullptr);
}

// --- Stage 4: out[b] = M[b] @ phi_k[b] + bo ; grid (32, 2, 16) --------------
__global__ __launch_bounds__(256) void k_out(const float* __restrict__ bo,
                                             float* __restrict__ out)
{
    const int b = blockIdx.z;
    const float* A = g_M + (size_t)b * NC * NC + (size_t)(blockIdx.y * 128) * NC;
    const float* B = g_phi + (size_t)b * PHI_B + (size_t)256 * NPIX + blockIdx.x * 128;
    float* C = out + (size_t)b * NC * NPIX + (size_t)(blockIdx.y * 128) * NPIX + blockIdx.x * 128;
    gemm_tile_tc<false, 2>(A, NC, B, NPIX, C, NPIX, NC, bo + blockIdx.y * 128);
}

// ---------------------------------------------------------------------------
extern "C" void kernel_launch(void* const* d_in, const int* in_sizes, int n_in,
                              void* d_out, int out_size)
{
    const float* x  = (const float*)d_in[0];
    const float* Wq = (const float*)d_in[1];
    const float* Wk = (const float*)d_in[2];
    const float* Wv = (const float*)d_in[3];
    const float* Wo = (const float*)d_in[4];
    const float* bo = (const float*)d_in[5];
    float* out = (float*)d_out;

    k_qkv<<<dim3(32, 6, 16), 256>>>(x, Wq, Wk, Wv);
    k_qv<<<dim3(2, 2, NB * KSPLIT), 256>>>();
    k_qv_reduce<<<dim3(QV_N / 256), 256>>>();
    k_m<<<dim3(2, 2, 16), 256>>>(Wo);
    k_out<<<dim3(32, 2, 16), 256>>>(bo, out);
}